// round 5
// baseline (speedup 1.0000x reference)
#include <cuda_runtime.h>
#include <cuda_bf16.h>
#include <mma.h>
#include <cstdint>
#include <math.h>

using namespace nvcuda;
typedef __nv_bfloat16 bf16;

// Problem constants (fixed shapes)
#define TOK   131072      // B*H*W = 8*128*128
#define CDIM  192
#define HID   768
#define QKVN  576
#define NHEAD 6
#define SS    4
#define NWIN  2048        // B * 16 * 16

// GEMM tiling
#define BM 256
#define BN 64
#define BK 32
#define LDA 40            // A tile ld (bf16): 80B rows
#define LDB 72            // B tile ld (bf16): 144B rows
#define LDC 68            // C tile ld (fp32)
#define A_STAGE_BYTES (BM * LDA * 2)            // 20480
#define B_STAGE_BYTES (BK * LDB * 2)            // 4608
#define STAGE_BYTES   (A_STAGE_BYTES + B_STAGE_BYTES)   // 25088
#define NSTAGE 3
#define SMEM_TOTAL (NSTAGE * STAGE_BYTES)       // 75264 (>= C tile 256*68*4=69632)

// ---------------- scratch (device globals; no allocations allowed) ----------
__device__ bf16  g_xbf[TOK * CDIM];        // bf16 copy of x
__device__ bf16  g_qkv[TOK * QKVN];        // window-ordered, bf16
__device__ bf16  g_attnout[TOK * CDIM];    // window-ordered, bf16
__device__ float g_x1[TOK * CDIM];         // x + attn branch (fp32, global order)
__device__ bf16  g_x1n[TOK * CDIM];        // LN(x1)*g+b, bf16
__device__ bf16  g_h[TOK * HID];           // gelu(fc1), bf16
__device__ bf16  g_wqkv[CDIM * QKVN];      // bf16 weights, [K][N]
__device__ bf16  g_wproj[CDIM * CDIM];
__device__ bf16  g_w1[CDIM * HID];
__device__ bf16  g_w2[HID * CDIM];

// ---------------- helpers ----------------------------------------------------
__device__ __forceinline__ uint32_t smem_u32(const void* p) {
    uint32_t a;
    asm("{ .reg .u64 t; cvta.to.shared.u64 t, %1; cvt.u32.u64 %0, t; }" : "=r"(a) : "l"(p));
    return a;
}
#define CP_ASYNC16(dst, src) \
    asm volatile("cp.async.cg.shared.global [%0], [%1], 16;" :: "r"(dst), "l"(src))
#define CP_COMMIT() asm volatile("cp.async.commit_group;" ::: "memory")
#define CP_WAIT(n)  asm volatile("cp.async.wait_group %0;" :: "n"(n) : "memory")

__device__ __forceinline__ int map_win_to_global(int r) {
    int w = r >> 6, n = r & 63;
    int b = w >> 8, rem = w & 255;
    int wh = rem >> 4, ww = rem & 15;
    int i = n >> 3, j = n & 7;
    int h  = (wh * 8 + i + SS) & 127;
    int wc = (ww * 8 + j + SS) & 127;
    return (b << 14) + (h << 7) + wc;
}
__device__ __forceinline__ float gelu_exact(float v) {
    return 0.5f * v * (1.0f + erff(v * 0.70710678118654752440f));
}
__device__ __forceinline__ uint32_t pack_bf2(float a, float b) {
    __nv_bfloat162 h = __floats2bfloat162_rn(a, b);
    return *(uint32_t*)&h;
}

// ---------------- fp32 -> bf16 conversion -------------------------------------
__global__ void __launch_bounds__(256) conv_x_k(const float* __restrict__ src) {
    const size_t i = ((size_t)blockIdx.x * 256 + threadIdx.x) * 8;
    float4 v0 = *(const float4*)(src + i);
    float4 v1 = *(const float4*)(src + i + 4);
    uint4 o;
    o.x = pack_bf2(v0.x, v0.y); o.y = pack_bf2(v0.z, v0.w);
    o.z = pack_bf2(v1.x, v1.y); o.w = pack_bf2(v1.z, v1.w);
    *(uint4*)(g_xbf + i) = o;
}
// all four weights in one launch;每 thread converts one 8-elem chunk
#define S0 (CDIM*QKVN)
#define S1 (CDIM*CDIM)
#define S2 (CDIM*HID)
#define S3 (HID*CDIM)
__global__ void __launch_bounds__(256) conv_w_all(
    const float* __restrict__ w0, const float* __restrict__ w1,
    const float* __restrict__ w2, const float* __restrict__ w3)
{
    const int off = (blockIdx.x * 256 + threadIdx.x) * 8;
    const float* src; bf16* dst; int lo;
    if      (off < S0)            { src = w0; dst = g_wqkv;  lo = off; }
    else if (off < S0+S1)         { src = w1; dst = g_wproj; lo = off - S0; }
    else if (off < S0+S1+S2)      { src = w2; dst = g_w1;    lo = off - S0 - S1; }
    else if (off < S0+S1+S2+S3)   { src = w3; dst = g_w2;    lo = off - S0 - S1 - S2; }
    else return;
    float4 v0 = *(const float4*)(src + lo);
    float4 v1 = *(const float4*)(src + lo + 4);
    uint4 o;
    o.x = pack_bf2(v0.x, v0.y); o.y = pack_bf2(v0.z, v0.w);
    o.z = pack_bf2(v1.x, v1.y); o.w = pack_bf2(v1.z, v1.w);
    *(uint4*)(dst + lo) = o;
}

// ---------------- WMMA bf16 GEMM, 3-stage cp.async ----------------------------
// MODE: 0=QKV(gather A; out bf16 g_qkv)  1=PROJ(scatter+resid -> fp32 g_x1)
//       2=FC1(gelu -> bf16 g_h)          3=FC2(+resid g_x1 -> fp32 Cout)
template<int KDIM, int NDIM, int MODE>
__global__ void __launch_bounds__(256, 2) gemm_bf(
    const float* __restrict__ bias,
    const float* __restrict__ resid,
    float* __restrict__ Cout)
{
    extern __shared__ __align__(16) unsigned char dsm[];
    float* sC = (float*)dsm;

    const int tid = threadIdx.x;
    const int bm = blockIdx.y * BM;
    const int bn = blockIdx.x * BN;

    const bf16* Aptr;
    const bf16* Bptr;
    if      constexpr (MODE == 0) { Aptr = g_xbf;     Bptr = g_wqkv; }
    else if constexpr (MODE == 1) { Aptr = g_attnout; Bptr = g_wproj; }
    else if constexpr (MODE == 2) { Aptr = g_x1n;     Bptr = g_w1; }
    else                          { Aptr = g_h;       Bptr = g_w2; }

    // A: thread t owns tile row t (32 bf16 = 4 x 16B chunks per stage)
    int grA;
    if constexpr (MODE == 0) grA = map_win_to_global(bm + tid);
    else                     grA = bm + tid;
    const bf16* srcA = Aptr + (size_t)grA * KDIM;
    const uint32_t dA = smem_u32(dsm) + (uint32_t)(tid * (LDA * 2));
    // B: 32 rows x 64 bf16 = 256 chunks; thread owns one chunk
    const int bR = tid >> 3, bC = (tid & 7) * 8;
    const bf16* srcB = Bptr + (size_t)bR * NDIM + bn + bC;
    const uint32_t dB = smem_u32(dsm) + (uint32_t)(A_STAGE_BYTES + (bR * LDB + bC) * 2);

    constexpr int T = KDIM / BK;
    const int wid = tid >> 5;
    const int wm = wid & 3, wn = wid >> 2;   // 4x2 warps, warp tile 64x32

    wmma::fragment<wmma::accumulator, 16, 16, 16, float> cf[4][2];
    #pragma unroll
    for (int i = 0; i < 4; i++)
        #pragma unroll
        for (int j = 0; j < 2; j++) wmma::fill_fragment(cf[i][j], 0.0f);

    // prologue: prefetch stages 0,1
    #pragma unroll
    for (int s = 0; s < 2; s++) {
        const int k0 = s * BK;
        const uint32_t so = s * STAGE_BYTES;
        #pragma unroll
        for (int c = 0; c < 4; c++) CP_ASYNC16(dA + so + c * 16, srcA + k0 + c * 8);
        CP_ASYNC16(dB + so, srcB + (size_t)k0 * NDIM);
        CP_COMMIT();
    }

    #pragma unroll 2
    for (int t = 0; t < T; t++) {
        CP_WAIT(1);
        __syncthreads();
        if (t + 2 < T) {
            const int k0 = (t + 2) * BK;
            const uint32_t so = ((t + 2) % NSTAGE) * STAGE_BYTES;
            #pragma unroll
            for (int c = 0; c < 4; c++) CP_ASYNC16(dA + so + c * 16, srcA + k0 + c * 8);
            CP_ASYNC16(dB + so, srcB + (size_t)k0 * NDIM);
        }
        CP_COMMIT();   // commit every iter to keep group accounting uniform

        const bf16* At = (const bf16*)(dsm + (t % NSTAGE) * STAGE_BYTES);
        const bf16* Bt = (const bf16*)(dsm + (t % NSTAGE) * STAGE_BYTES + A_STAGE_BYTES);

        #pragma unroll
        for (int kk = 0; kk < BK; kk += 16) {
            wmma::fragment<wmma::matrix_a, 16, 16, 16, bf16, wmma::row_major> af[4];
            wmma::fragment<wmma::matrix_b, 16, 16, 16, bf16, wmma::row_major> bf_[2];
            #pragma unroll
            for (int i = 0; i < 4; i++)
                wmma::load_matrix_sync(af[i], At + (wm * 64 + i * 16) * LDA + kk, LDA);
            #pragma unroll
            for (int j = 0; j < 2; j++)
                wmma::load_matrix_sync(bf_[j], Bt + kk * LDB + wn * 32 + j * 16, LDB);
            #pragma unroll
            for (int i = 0; i < 4; i++)
                #pragma unroll
                for (int j = 0; j < 2; j++)
                    wmma::mma_sync(cf[i][j], af[i], bf_[j], cf[i][j]);
        }
        __syncthreads();   // protect smem stage about to be overwritten
    }

    // accumulators -> smem C tile (reuses pipeline smem; compute done)
    #pragma unroll
    for (int i = 0; i < 4; i++)
        #pragma unroll
        for (int j = 0; j < 2; j++)
            wmma::store_matrix_sync(sC + (wm * 64 + i * 16) * LDC + wn * 32 + j * 16,
                                    cf[i][j], LDC, wmma::mem_row_major);
    __syncthreads();

    // epilogue: thread t owns output row t (64 cols)
    const int m = bm + tid;
    float v[64];
    #pragma unroll
    for (int c4 = 0; c4 < 16; c4++) {
        float4 w4 = *(const float4*)(sC + tid * LDC + c4 * 4);
        v[c4*4+0] = w4.x + __ldg(bias + bn + c4*4 + 0);
        v[c4*4+1] = w4.y + __ldg(bias + bn + c4*4 + 1);
        v[c4*4+2] = w4.z + __ldg(bias + bn + c4*4 + 2);
        v[c4*4+3] = w4.w + __ldg(bias + bn + c4*4 + 3);
    }

    if constexpr (MODE == 0) {
        bf16* dst = g_qkv + (size_t)m * QKVN + bn;
        #pragma unroll
        for (int g = 0; g < 8; g++) {
            uint4 o;
            o.x = pack_bf2(v[g*8+0], v[g*8+1]); o.y = pack_bf2(v[g*8+2], v[g*8+3]);
            o.z = pack_bf2(v[g*8+4], v[g*8+5]); o.w = pack_bf2(v[g*8+6], v[g*8+7]);
            *(uint4*)(dst + g * 8) = o;
        }
    } else if constexpr (MODE == 1) {
        const int grow = map_win_to_global(m);
        const size_t o = (size_t)grow * CDIM + bn;
        #pragma unroll
        for (int c4 = 0; c4 < 16; c4++) {
            float4 r = *(const float4*)(resid + o + c4 * 4);
            *(float4*)(g_x1 + o + c4 * 4) =
                make_float4(v[c4*4+0] + r.x, v[c4*4+1] + r.y, v[c4*4+2] + r.z, v[c4*4+3] + r.w);
        }
    } else if constexpr (MODE == 2) {
        bf16* dst = g_h + (size_t)m * HID + bn;
        #pragma unroll
        for (int g = 0; g < 8; g++) {
            uint4 o;
            o.x = pack_bf2(gelu_exact(v[g*8+0]), gelu_exact(v[g*8+1]));
            o.y = pack_bf2(gelu_exact(v[g*8+2]), gelu_exact(v[g*8+3]));
            o.z = pack_bf2(gelu_exact(v[g*8+4]), gelu_exact(v[g*8+5]));
            o.w = pack_bf2(gelu_exact(v[g*8+6]), gelu_exact(v[g*8+7]));
            *(uint4*)(dst + g * 8) = o;
        }
    } else {
        const size_t o = (size_t)m * CDIM + bn;
        #pragma unroll
        for (int c4 = 0; c4 < 16; c4++) {
            float4 r = *(const float4*)(g_x1 + o + c4 * 4);
            *(float4*)(Cout + o + c4 * 4) =
                make_float4(v[c4*4+0] + r.x, v[c4*4+1] + r.y, v[c4*4+2] + r.z, v[c4*4+3] + r.w);
        }
    }
}

// ---------------- LayerNorm: one warp per token, bf16 out ---------------------
__global__ void __launch_bounds__(256) ln_norm_k(const float* __restrict__ gamma,
                                                 const float* __restrict__ beta)
{
    const int r = blockIdx.x * 8 + (threadIdx.x >> 5);
    const int lane = threadIdx.x & 31;
    const float* p = g_x1 + (size_t)r * CDIM;
    float v[6];
    float s = 0.f, ss = 0.f;
    #pragma unroll
    for (int k = 0; k < 6; k++) {
        v[k] = p[lane + k * 32];
        s += v[k]; ss += v[k] * v[k];
    }
    #pragma unroll
    for (int o = 16; o; o >>= 1) {
        s  += __shfl_xor_sync(0xffffffffu, s,  o);
        ss += __shfl_xor_sync(0xffffffffu, ss, o);
    }
    const float mu = s * (1.f / 192.f);
    const float var = ss * (1.f / 192.f) - mu * mu;
    const float rs = rsqrtf(var + 1e-5f);
    bf16* q = g_x1n + (size_t)r * CDIM;
    #pragma unroll
    for (int k = 0; k < 6; k++) {
        const int c = lane + k * 32;
        q[c] = __float2bfloat16_rn((v[k] - mu) * rs * __ldg(gamma + c) + __ldg(beta + c));
    }
}

// ---------------- attention: one block per (window, head), bf16 in/out --------
__global__ void __launch_bounds__(64) attn_k(const float* __restrict__ rpb)
{
    const int w = blockIdx.x, head = blockIdx.y, t = threadIdx.x;
    __shared__ float sK[64][32];
    __shared__ float sV[64][32];
    __shared__ float sS[64][65];
    __shared__ float sRp[225];
    __shared__ int   sReg[64];

    const bf16* base = g_qkv + (size_t)w * 64 * QKVN + head * 32;
    #pragma unroll
    for (int l = 0; l < 4; l++) {
        int i = t + l * 64;
        int n = i >> 2, cg = (i & 3) * 8;
        uint4 kc = *(const uint4*)(base + (size_t)n * QKVN + CDIM     + cg);
        uint4 vc = *(const uint4*)(base + (size_t)n * QKVN + 2*CDIM   + cg);
        const __nv_bfloat162* kp = (const __nv_bfloat162*)&kc;
        const __nv_bfloat162* vp = (const __nv_bfloat162*)&vc;
        #pragma unroll
        for (int u = 0; u < 4; u++) {
            float2 kf = __bfloat1622float2(kp[u]);
            float2 vf = __bfloat1622float2(vp[u]);
            sK[n][cg + u*2 + 0] = kf.x; sK[n][cg + u*2 + 1] = kf.y;
            sV[n][cg + u*2 + 0] = vf.x; sV[n][cg + u*2 + 1] = vf.y;
        }
    }
    for (int i = t; i < 225; i += 64) sRp[i] = rpb[i * NHEAD + head];
    {
        int rem = w & 255; int wh = rem >> 4, ww = rem & 15;
        int hs  = wh * 8 + (t >> 3);
        int wsc = ww * 8 + (t & 7);
        int rh = hs  < 120 ? 0 : (hs  < 124 ? 1 : 2);
        int rw = wsc < 120 ? 0 : (wsc < 124 ? 1 : 2);
        sReg[t] = rh * 3 + rw;
    }
    float qr[32];
    {
        const bf16* qp = g_qkv + ((size_t)w * 64 + t) * QKVN + head * 32;
        #pragma unroll
        for (int g = 0; g < 4; g++) {
            uint4 qc = *(const uint4*)(qp + g * 8);
            const __nv_bfloat162* pp = (const __nv_bfloat162*)&qc;
            #pragma unroll
            for (int u = 0; u < 4; u++) {
                float2 f = __bfloat1622float2(pp[u]);
                qr[g*8 + u*2 + 0] = f.x; qr[g*8 + u*2 + 1] = f.y;
            }
        }
    }
    __syncthreads();

    const int i1 = t >> 3, j1 = t & 7;
    const int regt = sReg[t];
    const float scale = 0.17677669529663689f;

    for (int m = 0; m < 64; m++) {
        float acc = 0.f;
        #pragma unroll
        for (int d4 = 0; d4 < 8; d4++) {
            float4 kk = *(const float4*)&sK[m][d4 * 4];
            acc += qr[d4*4+0]*kk.x + qr[d4*4+1]*kk.y + qr[d4*4+2]*kk.z + qr[d4*4+3]*kk.w;
        }
        int i2 = m >> 3, j2 = m & 7;
        float b = sRp[(i1 - i2 + 7) * 15 + (j1 - j2 + 7)];
        float msk = (sReg[m] == regt) ? 0.f : -100.f;
        sS[t][m] = acc * scale + b + msk;
    }
    float mx = -1e30f;
    for (int m = 0; m < 64; m++) mx = fmaxf(mx, sS[t][m]);
    float sum = 0.f;
    for (int m = 0; m < 64; m++) { float e = __expf(sS[t][m] - mx); sS[t][m] = e; sum += e; }
    float inv = 1.f / sum;

    float acc[32];
    #pragma unroll
    for (int d = 0; d < 32; d++) acc[d] = 0.f;
    for (int m = 0; m < 64; m++) {
        float p = sS[t][m];
        #pragma unroll
        for (int d4 = 0; d4 < 8; d4++) {
            float4 vv = *(const float4*)&sV[m][d4 * 4];
            acc[d4*4+0] += p * vv.x; acc[d4*4+1] += p * vv.y;
            acc[d4*4+2] += p * vv.z; acc[d4*4+3] += p * vv.w;
        }
    }
    bf16* op = g_attnout + ((size_t)w * 64 + t) * CDIM + head * 32;
    #pragma unroll
    for (int g = 0; g < 4; g++) {
        uint2 o, o2;
        o.x  = pack_bf2(acc[g*8+0]*inv, acc[g*8+1]*inv);
        o.y  = pack_bf2(acc[g*8+2]*inv, acc[g*8+3]*inv);
        o2.x = pack_bf2(acc[g*8+4]*inv, acc[g*8+5]*inv);
        o2.y = pack_bf2(acc[g*8+6]*inv, acc[g*8+7]*inv);
        *(uint2*)(op + g * 8)     = o;
        *(uint2*)(op + g * 8 + 4) = o2;
    }
}

// ---------------- launch -----------------------------------------------------
extern "C" void kernel_launch(void* const* d_in, const int* in_sizes, int n_in,
                              void* d_out, int out_size)
{
    const float* x       = (const float*)d_in[0];
    const float* qkv_w   = (const float*)d_in[1];
    const float* qkv_b   = (const float*)d_in[2];
    const float* proj_w  = (const float*)d_in[3];
    const float* proj_b  = (const float*)d_in[4];
    const float* rpb     = (const float*)d_in[5];
    const float* norm2_g = (const float*)d_in[6];
    const float* norm2_b = (const float*)d_in[7];
    const float* mlp_w1  = (const float*)d_in[8];
    const float* mlp_b1  = (const float*)d_in[9];
    const float* mlp_w2  = (const float*)d_in[10];
    const float* mlp_b2  = (const float*)d_in[11];
    float* out = (float*)d_out;

    cudaFuncSetAttribute(gemm_bf<192, 576, 0>, cudaFuncAttributeMaxDynamicSharedMemorySize, SMEM_TOTAL);
    cudaFuncSetAttribute(gemm_bf<192, 192, 1>, cudaFuncAttributeMaxDynamicSharedMemorySize, SMEM_TOTAL);
    cudaFuncSetAttribute(gemm_bf<192, 768, 2>, cudaFuncAttributeMaxDynamicSharedMemorySize, SMEM_TOTAL);
    cudaFuncSetAttribute(gemm_bf<768, 192, 3>, cudaFuncAttributeMaxDynamicSharedMemorySize, SMEM_TOTAL);

    // precision conversions
    conv_x_k<<<TOK * CDIM / (256 * 8), 256>>>(x);
    conv_w_all<<<(S0 + S1 + S2 + S3) / (256 * 8), 256>>>(qkv_w, proj_w, mlp_w1, mlp_w2);

    // 1) QKV = gather(x) @ qkv_w + b  -> bf16 g_qkv (window order)
    gemm_bf<192, 576, 0><<<dim3(9, 512), 256, SMEM_TOTAL>>>(qkv_b, nullptr, nullptr);
    // 2) windowed attention -> bf16 g_attnout
    attn_k<<<dim3(NWIN, NHEAD), 64>>>(rpb);
    // 3) proj + scatter + residual -> fp32 g_x1
    gemm_bf<192, 192, 1><<<dim3(3, 512), 256, SMEM_TOTAL>>>(proj_b, x, nullptr);
    // 4) LayerNorm(g_x1) -> bf16 g_x1n
    ln_norm_k<<<TOK / 8, 256>>>(norm2_g, norm2_b);
    // 5) fc1 + GELU -> bf16 g_h
    gemm_bf<192, 768, 2><<<dim3(12, 512), 256, SMEM_TOTAL>>>(mlp_b1, nullptr, nullptr);
    // 6) fc2 + residual -> fp32 out
    gemm_bf<768, 192, 3><<<dim3(3, 512), 256, SMEM_TOTAL>>>(mlp_b2, nullptr, out);
}

// round 6
// speedup vs baseline: 1.0856x; 1.0856x over previous
#include <cuda_runtime.h>
#include <cuda_bf16.h>
#include <mma.h>
#include <cstdint>
#include <math.h>

using namespace nvcuda;
typedef __nv_bfloat16 bf16;

// Problem constants (fixed shapes)
#define TOK   131072      // B*H*W = 8*128*128
#define CDIM  192
#define HID   768
#define QKVN  576
#define NHEAD 6
#define SS    4
#define NWIN  2048        // B * 16 * 16

// GEMM tiling (round-4 proven config)
#define BM 128
#define BN 64
#define BK 32
#define LDA 40            // A tile ld (bf16)
#define LDB 72            // B tile ld (bf16)
#define LDC 68            // C tile ld (fp32)
#define A_STAGE_B (BM * LDA * 2)      // 10240 bytes
#define B_STAGE_B (BK * LDB * 2)      // 4608 bytes
#define SMEM_BYTES (BM * LDC * 4)     // 34816 (C tile unions over 2-stage A/B)

// ---------------- scratch (device globals; no allocations allowed) ----------
__device__ bf16  g_xbf[TOK * CDIM];
__device__ bf16  g_qkv[TOK * QKVN];        // window-ordered, bf16
__device__ bf16  g_attnout[TOK * CDIM];    // window-ordered, bf16
__device__ float g_x1[TOK * CDIM];         // fp32 residual spine
__device__ bf16  g_x1n[TOK * CDIM];
__device__ bf16  g_h[TOK * HID];
__device__ bf16  g_wqkv[CDIM * QKVN];
__device__ bf16  g_wproj[CDIM * CDIM];
__device__ bf16  g_w1[CDIM * HID];
__device__ bf16  g_w2[HID * CDIM];

// ---------------- helpers ----------------------------------------------------
__device__ __forceinline__ uint32_t smem_u32(const void* p) {
    uint32_t a;
    asm("{ .reg .u64 t; cvta.to.shared.u64 t, %1; cvt.u32.u64 %0, t; }" : "=r"(a) : "l"(p));
    return a;
}
#define CP_ASYNC16(dst, src) \
    asm volatile("cp.async.cg.shared.global [%0], [%1], 16;" :: "r"(dst), "l"(src))
#define CP_COMMIT() asm volatile("cp.async.commit_group;" ::: "memory")
#define CP_WAIT(n)  asm volatile("cp.async.wait_group %0;" :: "n"(n) : "memory")

__device__ __forceinline__ int map_win_to_global(int r) {
    int w = r >> 6, n = r & 63;
    int b = w >> 8, rem = w & 255;
    int wh = rem >> 4, ww = rem & 15;
    int i = n >> 3, j = n & 7;
    int h  = (wh * 8 + i + SS) & 127;
    int wc = (ww * 8 + j + SS) & 127;
    return (b << 14) + (h << 7) + wc;
}
__device__ __forceinline__ float gelu_exact(float v) {
    return 0.5f * v * (1.0f + erff(v * 0.70710678118654752440f));
}
__device__ __forceinline__ uint32_t pack_bf2(float a, float b) {
    __nv_bfloat162 h = __floats2bfloat162_rn(a, b);
    return *(uint32_t*)&h;
}

// ---------------- fp32 -> bf16 conversion -------------------------------------
__global__ void __launch_bounds__(256) conv_x_k(const float* __restrict__ src) {
    const size_t i = ((size_t)blockIdx.x * 256 + threadIdx.x) * 8;
    float4 v0 = *(const float4*)(src + i);
    float4 v1 = *(const float4*)(src + i + 4);
    uint4 o;
    o.x = pack_bf2(v0.x, v0.y); o.y = pack_bf2(v0.z, v0.w);
    o.z = pack_bf2(v1.x, v1.y); o.w = pack_bf2(v1.z, v1.w);
    *(uint4*)(g_xbf + i) = o;
}
#define S0 (CDIM*QKVN)
#define S1 (CDIM*CDIM)
#define S2 (CDIM*HID)
#define S3 (HID*CDIM)
__global__ void __launch_bounds__(256) conv_w_all(
    const float* __restrict__ w0, const float* __restrict__ w1,
    const float* __restrict__ w2, const float* __restrict__ w3)
{
    const int off = (blockIdx.x * 256 + threadIdx.x) * 8;
    const float* src; bf16* dst; int lo;
    if      (off < S0)            { src = w0; dst = g_wqkv;  lo = off; }
    else if (off < S0+S1)         { src = w1; dst = g_wproj; lo = off - S0; }
    else if (off < S0+S1+S2)      { src = w2; dst = g_w1;    lo = off - S0 - S1; }
    else if (off < S0+S1+S2+S3)   { src = w3; dst = g_w2;    lo = off - S0 - S1 - S2; }
    else return;
    float4 v0 = *(const float4*)(src + lo);
    float4 v1 = *(const float4*)(src + lo + 4);
    uint4 o;
    o.x = pack_bf2(v0.x, v0.y); o.y = pack_bf2(v0.z, v0.w);
    o.z = pack_bf2(v1.x, v1.y); o.w = pack_bf2(v1.z, v1.w);
    *(uint4*)(dst + lo) = o;
}

// ---------------- WMMA bf16 GEMM (round-4 config: BM=128, 2-stage) ------------
// MODE: 0=QKV(gather A; out bf16 g_qkv)  1=PROJ(scatter+resid -> fp32 g_x1)
//       2=FC1(gelu -> bf16 g_h)          3=FC2(+resid g_x1 -> fp32 Cout)
template<int KDIM, int NDIM, int MODE>
__global__ void __launch_bounds__(128) gemm_bf(
    const float* __restrict__ bias,
    const float* __restrict__ resid,
    float* __restrict__ Cout)
{
    __shared__ __align__(16) unsigned char smem[SMEM_BYTES];
    bf16* sA = (bf16*)smem;
    bf16* sB = (bf16*)(smem + 2 * A_STAGE_B);
    float* sC = (float*)smem;

    const int tid = threadIdx.x;
    const int bm = blockIdx.y * BM;
    const int bn = blockIdx.x * BN;

    const bf16* Aptr;
    const bf16* Bptr;
    if      constexpr (MODE == 0) { Aptr = g_xbf;     Bptr = g_wqkv; }
    else if constexpr (MODE == 1) { Aptr = g_attnout; Bptr = g_wproj; }
    else if constexpr (MODE == 2) { Aptr = g_x1n;     Bptr = g_w1; }
    else                          { Aptr = g_h;       Bptr = g_w2; }

    int grA;
    if constexpr (MODE == 0) grA = map_win_to_global(bm + tid);
    else                     grA = bm + tid;
    const bf16* srcA = Aptr + (size_t)grA * KDIM;
    const uint32_t dA = smem_u32(sA) + (uint32_t)(tid * LDA * 2);

    const int bR0 = tid >> 3,         bC0 = (tid & 7) * 8;
    const int bR1 = (tid + 128) >> 3, bC1 = (tid & 7) * 8;
    const bf16* srcB0 = Bptr + (size_t)bR0 * NDIM + bn + bC0;
    const bf16* srcB1 = Bptr + (size_t)bR1 * NDIM + bn + bC1;
    const uint32_t dB0 = smem_u32(sB) + (uint32_t)((bR0 * LDB + bC0) * 2);
    const uint32_t dB1 = smem_u32(sB) + (uint32_t)((bR1 * LDB + bC1) * 2);

    constexpr int T = KDIM / BK;
    const int wid = tid >> 5;
    const int wm = wid & 1, wn = wid >> 1;   // 2x2 warps, warp tile 64x32

    wmma::fragment<wmma::accumulator, 16, 16, 16, float> cf[4][2];
    #pragma unroll
    for (int i = 0; i < 4; i++)
        #pragma unroll
        for (int j = 0; j < 2; j++) wmma::fill_fragment(cf[i][j], 0.0f);

    #pragma unroll
    for (int c = 0; c < 4; c++) CP_ASYNC16(dA + c * 16, srcA + c * 8);
    CP_ASYNC16(dB0, srcB0);
    CP_ASYNC16(dB1, srcB1);
    CP_COMMIT();

    for (int t = 0; t < T; t++) {
        if (t + 1 < T) {
            const int k0 = (t + 1) * BK;
            const uint32_t soA = ((t + 1) & 1) ? A_STAGE_B : 0;
            const uint32_t soB = ((t + 1) & 1) ? B_STAGE_B : 0;
            #pragma unroll
            for (int c = 0; c < 4; c++) CP_ASYNC16(dA + soA + c * 16, srcA + k0 + c * 8);
            CP_ASYNC16(dB0 + soB, srcB0 + (size_t)k0 * NDIM);
            CP_ASYNC16(dB1 + soB, srcB1 + (size_t)k0 * NDIM);
            CP_COMMIT();
            CP_WAIT(1);
        } else {
            CP_WAIT(0);
        }
        __syncthreads();

        const bf16* At = sA + ((t & 1) ? BM * LDA : 0);
        const bf16* Bt = sB + ((t & 1) ? BK * LDB : 0);

        #pragma unroll
        for (int kk = 0; kk < BK; kk += 16) {
            wmma::fragment<wmma::matrix_a, 16, 16, 16, bf16, wmma::row_major> af[4];
            wmma::fragment<wmma::matrix_b, 16, 16, 16, bf16, wmma::row_major> bf_[2];
            #pragma unroll
            for (int i = 0; i < 4; i++)
                wmma::load_matrix_sync(af[i], At + (wm * 64 + i * 16) * LDA + kk, LDA);
            #pragma unroll
            for (int j = 0; j < 2; j++)
                wmma::load_matrix_sync(bf_[j], Bt + kk * LDB + wn * 32 + j * 16, LDB);
            #pragma unroll
            for (int i = 0; i < 4; i++)
                #pragma unroll
                for (int j = 0; j < 2; j++)
                    wmma::mma_sync(cf[i][j], af[i], bf_[j], cf[i][j]);
        }
        __syncthreads();
    }

    #pragma unroll
    for (int i = 0; i < 4; i++)
        #pragma unroll
        for (int j = 0; j < 2; j++)
            wmma::store_matrix_sync(sC + (wm * 64 + i * 16) * LDC + wn * 32 + j * 16,
                                    cf[i][j], LDC, wmma::mem_row_major);
    __syncthreads();

    const int m = bm + tid;
    float v[64];
    #pragma unroll
    for (int c4 = 0; c4 < 16; c4++) {
        float4 w4 = *(const float4*)(sC + tid * LDC + c4 * 4);
        v[c4*4+0] = w4.x + __ldg(bias + bn + c4*4 + 0);
        v[c4*4+1] = w4.y + __ldg(bias + bn + c4*4 + 1);
        v[c4*4+2] = w4.z + __ldg(bias + bn + c4*4 + 2);
        v[c4*4+3] = w4.w + __ldg(bias + bn + c4*4 + 3);
    }

    if constexpr (MODE == 0) {
        bf16* dst = g_qkv + (size_t)m * QKVN + bn;
        #pragma unroll
        for (int g = 0; g < 8; g++) {
            uint4 o;
            o.x = pack_bf2(v[g*8+0], v[g*8+1]); o.y = pack_bf2(v[g*8+2], v[g*8+3]);
            o.z = pack_bf2(v[g*8+4], v[g*8+5]); o.w = pack_bf2(v[g*8+6], v[g*8+7]);
            *(uint4*)(dst + g * 8) = o;
        }
    } else if constexpr (MODE == 1) {
        const int grow = map_win_to_global(m);
        const size_t o = (size_t)grow * CDIM + bn;
        #pragma unroll
        for (int c4 = 0; c4 < 16; c4++) {
            float4 r = *(const float4*)(resid + o + c4 * 4);
            *(float4*)(g_x1 + o + c4 * 4) =
                make_float4(v[c4*4+0] + r.x, v[c4*4+1] + r.y, v[c4*4+2] + r.z, v[c4*4+3] + r.w);
        }
    } else if constexpr (MODE == 2) {
        bf16* dst = g_h + (size_t)m * HID + bn;
        #pragma unroll
        for (int g = 0; g < 8; g++) {
            uint4 o;
            o.x = pack_bf2(gelu_exact(v[g*8+0]), gelu_exact(v[g*8+1]));
            o.y = pack_bf2(gelu_exact(v[g*8+2]), gelu_exact(v[g*8+3]));
            o.z = pack_bf2(gelu_exact(v[g*8+4]), gelu_exact(v[g*8+5]));
            o.w = pack_bf2(gelu_exact(v[g*8+6]), gelu_exact(v[g*8+7]));
            *(uint4*)(dst + g * 8) = o;
        }
    } else {
        const size_t o = (size_t)m * CDIM + bn;
        #pragma unroll
        for (int c4 = 0; c4 < 16; c4++) {
            float4 r = *(const float4*)(g_x1 + o + c4 * 4);
            *(float4*)(Cout + o + c4 * 4) =
                make_float4(v[c4*4+0] + r.x, v[c4*4+1] + r.y, v[c4*4+2] + r.z, v[c4*4+3] + r.w);
        }
    }
}

// ---------------- LayerNorm: one warp per token, bf16 out ---------------------
__global__ void __launch_bounds__(256) ln_norm_k(const float* __restrict__ gamma,
                                                 const float* __restrict__ beta)
{
    const int r = blockIdx.x * 8 + (threadIdx.x >> 5);
    const int lane = threadIdx.x & 31;
    const float* p = g_x1 + (size_t)r * CDIM;
    float v[6];
    float s = 0.f, ss = 0.f;
    #pragma unroll
    for (int k = 0; k < 6; k++) {
        v[k] = p[lane + k * 32];
        s += v[k]; ss += v[k] * v[k];
    }
    #pragma unroll
    for (int o = 16; o; o >>= 1) {
        s  += __shfl_xor_sync(0xffffffffu, s,  o);
        ss += __shfl_xor_sync(0xffffffffu, ss, o);
    }
    const float mu = s * (1.f / 192.f);
    const float var = ss * (1.f / 192.f) - mu * mu;
    const float rs = rsqrtf(var + 1e-5f);
    bf16* q = g_x1n + (size_t)r * CDIM;
    #pragma unroll
    for (int k = 0; k < 6; k++) {
        const int c = lane + k * 32;
        q[c] = __float2bfloat16_rn((v[k] - mu) * rs * __ldg(gamma + c) + __ldg(beta + c));
    }
}

// ---------------- attention: single-pass, no score matrix ---------------------
// softmax(s) = exp(s)/Σexp(s) — no max subtraction (scores are O(1); masked
// entries are -100 → exp→0). Removes 16.6KB smem + 3 extra LDS passes.
__global__ void __launch_bounds__(64) attn_k(const float* __restrict__ rpb)
{
    const int w = blockIdx.x, head = blockIdx.y, t = threadIdx.x;
    __shared__ float sK[64][32];
    __shared__ float sV[64][32];
    __shared__ float sRp[225];
    __shared__ int   sReg[64];

    const bf16* base = g_qkv + (size_t)w * 64 * QKVN + head * 32;
    #pragma unroll
    for (int l = 0; l < 4; l++) {
        int i = t + l * 64;
        int n = i >> 2, cg = (i & 3) * 8;
        uint4 kc = *(const uint4*)(base + (size_t)n * QKVN + CDIM     + cg);
        uint4 vc = *(const uint4*)(base + (size_t)n * QKVN + 2*CDIM   + cg);
        const __nv_bfloat162* kp = (const __nv_bfloat162*)&kc;
        const __nv_bfloat162* vp = (const __nv_bfloat162*)&vc;
        #pragma unroll
        for (int u = 0; u < 4; u++) {
            float2 kf = __bfloat1622float2(kp[u]);
            float2 vf = __bfloat1622float2(vp[u]);
            sK[n][cg + u*2 + 0] = kf.x; sK[n][cg + u*2 + 1] = kf.y;
            sV[n][cg + u*2 + 0] = vf.x; sV[n][cg + u*2 + 1] = vf.y;
        }
    }
    for (int i = t; i < 225; i += 64) sRp[i] = rpb[i * NHEAD + head];
    {
        int rem = w & 255; int wh = rem >> 4, ww = rem & 15;
        int hs  = wh * 8 + (t >> 3);
        int wsc = ww * 8 + (t & 7);
        int rh = hs  < 120 ? 0 : (hs  < 124 ? 1 : 2);
        int rw = wsc < 120 ? 0 : (wsc < 124 ? 1 : 2);
        sReg[t] = rh * 3 + rw;
    }
    float qr[32];
    {
        const bf16* qp = g_qkv + ((size_t)w * 64 + t) * QKVN + head * 32;
        #pragma unroll
        for (int g = 0; g < 4; g++) {
            uint4 qc = *(const uint4*)(qp + g * 8);
            const __nv_bfloat162* pp = (const __nv_bfloat162*)&qc;
            #pragma unroll
            for (int u = 0; u < 4; u++) {
                float2 f = __bfloat1622float2(pp[u]);
                qr[g*8 + u*2 + 0] = f.x; qr[g*8 + u*2 + 1] = f.y;
            }
        }
    }
    __syncthreads();

    const int i1 = t >> 3, j1 = t & 7;
    const int regt = sReg[t];
    const float scale = 0.17677669529663689f;

    float sum = 0.f;
    float acc[32];
    #pragma unroll
    for (int d = 0; d < 32; d++) acc[d] = 0.f;

    for (int m = 0; m < 64; m++) {
        float s = 0.f;
        #pragma unroll
        for (int d4 = 0; d4 < 8; d4++) {
            float4 kk = *(const float4*)&sK[m][d4 * 4];
            s += qr[d4*4+0]*kk.x + qr[d4*4+1]*kk.y + qr[d4*4+2]*kk.z + qr[d4*4+3]*kk.w;
        }
        int i2 = m >> 3, j2 = m & 7;
        float b = sRp[(i1 - i2 + 7) * 15 + (j1 - j2 + 7)];
        float msk = (sReg[m] == regt) ? 0.f : -100.f;
        float e = __expf(s * scale + b + msk);
        sum += e;
        #pragma unroll
        for (int d4 = 0; d4 < 8; d4++) {
            float4 vv = *(const float4*)&sV[m][d4 * 4];
            acc[d4*4+0] += e * vv.x; acc[d4*4+1] += e * vv.y;
            acc[d4*4+2] += e * vv.z; acc[d4*4+3] += e * vv.w;
        }
    }
    const float inv = 1.f / sum;

    bf16* op = g_attnout + ((size_t)w * 64 + t) * CDIM + head * 32;
    #pragma unroll
    for (int g = 0; g < 4; g++) {
        uint2 o, o2;
        o.x  = pack_bf2(acc[g*8+0]*inv, acc[g*8+1]*inv);
        o.y  = pack_bf2(acc[g*8+2]*inv, acc[g*8+3]*inv);
        o2.x = pack_bf2(acc[g*8+4]*inv, acc[g*8+5]*inv);
        o2.y = pack_bf2(acc[g*8+6]*inv, acc[g*8+7]*inv);
        *(uint2*)(op + g * 8)     = o;
        *(uint2*)(op + g * 8 + 4) = o2;
    }
}

// ---------------- launch -----------------------------------------------------
extern "C" void kernel_launch(void* const* d_in, const int* in_sizes, int n_in,
                              void* d_out, int out_size)
{
    const float* x       = (const float*)d_in[0];
    const float* qkv_w   = (const float*)d_in[1];
    const float* qkv_b   = (const float*)d_in[2];
    const float* proj_w  = (const float*)d_in[3];
    const float* proj_b  = (const float*)d_in[4];
    const float* rpb     = (const float*)d_in[5];
    const float* norm2_g = (const float*)d_in[6];
    const float* norm2_b = (const float*)d_in[7];
    const float* mlp_w1  = (const float*)d_in[8];
    const float* mlp_b1  = (const float*)d_in[9];
    const float* mlp_w2  = (const float*)d_in[10];
    const float* mlp_b2  = (const float*)d_in[11];
    float* out = (float*)d_out;

    // precision conversions
    conv_x_k<<<TOK * CDIM / (256 * 8), 256>>>(x);
    conv_w_all<<<(S0 + S1 + S2 + S3) / (256 * 8), 256>>>(qkv_w, proj_w, mlp_w1, mlp_w2);

    // 1) QKV = gather(x) @ qkv_w + b  -> bf16 g_qkv (window order)
    gemm_bf<192, 576, 0><<<dim3(9, 1024), 128>>>(qkv_b, nullptr, nullptr);
    // 2) windowed attention -> bf16 g_attnout
    attn_k<<<dim3(NWIN, NHEAD), 64>>>(rpb);
    // 3) proj + scatter + residual -> fp32 g_x1
    gemm_bf<192, 192, 1><<<dim3(3, 1024), 128>>>(proj_b, x, nullptr);
    // 4) LayerNorm(g_x1) -> bf16 g_x1n
    ln_norm_k<<<TOK / 8, 256>>>(norm2_g, norm2_b);
    // 5) fc1 + GELU -> bf16 g_h
    gemm_bf<192, 768, 2><<<dim3(12, 1024), 128>>>(mlp_b1, nullptr, nullptr);
    // 6) fc2 + residual -> fp32 out
    gemm_bf<768, 192, 3><<<dim3(3, 1024), 128>>>(mlp_b2, nullptr, out);
}

// round 7
// speedup vs baseline: 1.2047x; 1.1097x over previous
#include <cuda_runtime.h>
#include <cuda_bf16.h>
#include <mma.h>
#include <cstdint>
#include <math.h>

using namespace nvcuda;
typedef __nv_bfloat16 bf16;

// Problem constants (fixed shapes)
#define TOK   131072      // B*H*W = 8*128*128
#define CDIM  192
#define HID   768
#define QKVN  576
#define NHEAD 6
#define SS    4
#define NWIN  2048        // B * 16 * 16

// GEMM tiling (proven config)
#define BM 128
#define BN 64
#define BK 32
#define LDA 40
#define LDB 72
#define LDC 68
#define A_STAGE_B (BM * LDA * 2)
#define B_STAGE_B (BK * LDB * 2)
#define SMEM_BYTES (BM * LDC * 4)

// ---------------- scratch (device globals; no allocations allowed) ----------
__device__ bf16  g_xbf[TOK * CDIM];
__device__ bf16  g_qkv[TOK * QKVN];        // window-ordered, bf16
__device__ bf16  g_attnout[TOK * CDIM];    // window-ordered, bf16
__device__ float g_x1[TOK * CDIM];         // fp32 residual spine
__device__ bf16  g_x1n[TOK * CDIM];
__device__ bf16  g_h[TOK * HID];
__device__ bf16  g_wqkv[CDIM * QKVN];
__device__ bf16  g_wproj[CDIM * CDIM];
__device__ bf16  g_w1[CDIM * HID];
__device__ bf16  g_w2[HID * CDIM];

// ---------------- helpers ----------------------------------------------------
__device__ __forceinline__ uint32_t smem_u32(const void* p) {
    uint32_t a;
    asm("{ .reg .u64 t; cvta.to.shared.u64 t, %1; cvt.u32.u64 %0, t; }" : "=r"(a) : "l"(p));
    return a;
}
#define CP_ASYNC16(dst, src) \
    asm volatile("cp.async.cg.shared.global [%0], [%1], 16;" :: "r"(dst), "l"(src))
#define CP_COMMIT() asm volatile("cp.async.commit_group;" ::: "memory")
#define CP_WAIT(n)  asm volatile("cp.async.wait_group %0;" :: "n"(n) : "memory")

__device__ __forceinline__ int map_win_to_global(int r) {
    int w = r >> 6, n = r & 63;
    int b = w >> 8, rem = w & 255;
    int wh = rem >> 4, ww = rem & 15;
    int i = n >> 3, j = n & 7;
    int h  = (wh * 8 + i + SS) & 127;
    int wc = (ww * 8 + j + SS) & 127;
    return (b << 14) + (h << 7) + wc;
}
__device__ __forceinline__ float gelu_exact(float v) {
    return 0.5f * v * (1.0f + erff(v * 0.70710678118654752440f));
}
__device__ __forceinline__ uint32_t pack_bf2(float a, float b) {
    __nv_bfloat162 h = __floats2bfloat162_rn(a, b);
    return *(uint32_t*)&h;
}

// ---------------- fp32 -> bf16 conversion -------------------------------------
__global__ void __launch_bounds__(256) conv_x_k(const float* __restrict__ src) {
    const size_t i = ((size_t)blockIdx.x * 256 + threadIdx.x) * 8;
    float4 v0 = *(const float4*)(src + i);
    float4 v1 = *(const float4*)(src + i + 4);
    uint4 o;
    o.x = pack_bf2(v0.x, v0.y); o.y = pack_bf2(v0.z, v0.w);
    o.z = pack_bf2(v1.x, v1.y); o.w = pack_bf2(v1.z, v1.w);
    *(uint4*)(g_xbf + i) = o;
}
#define S0 (CDIM*QKVN)
#define S1 (CDIM*CDIM)
#define S2 (CDIM*HID)
#define S3 (HID*CDIM)
__global__ void __launch_bounds__(256) conv_w_all(
    const float* __restrict__ w0, const float* __restrict__ w1,
    const float* __restrict__ w2, const float* __restrict__ w3)
{
    const int off = (blockIdx.x * 256 + threadIdx.x) * 8;
    const float* src; bf16* dst; int lo;
    if      (off < S0)            { src = w0; dst = g_wqkv;  lo = off; }
    else if (off < S0+S1)         { src = w1; dst = g_wproj; lo = off - S0; }
    else if (off < S0+S1+S2)      { src = w2; dst = g_w1;    lo = off - S0 - S1; }
    else if (off < S0+S1+S2+S3)   { src = w3; dst = g_w2;    lo = off - S0 - S1 - S2; }
    else return;
    float4 v0 = *(const float4*)(src + lo);
    float4 v1 = *(const float4*)(src + lo + 4);
    uint4 o;
    o.x = pack_bf2(v0.x, v0.y); o.y = pack_bf2(v0.z, v0.w);
    o.z = pack_bf2(v1.x, v1.y); o.w = pack_bf2(v1.z, v1.w);
    *(uint4*)(dst + lo) = o;
}

// ---------------- WMMA bf16 GEMM (BM=128, 2-stage) ----------------------------
template<int KDIM, int NDIM, int MODE>
__global__ void __launch_bounds__(128) gemm_bf(
    const float* __restrict__ bias,
    const float* __restrict__ resid,
    float* __restrict__ Cout)
{
    __shared__ __align__(16) unsigned char smem[SMEM_BYTES];
    bf16* sA = (bf16*)smem;
    bf16* sB = (bf16*)(smem + 2 * A_STAGE_B);
    float* sC = (float*)smem;

    const int tid = threadIdx.x;
    const int bm = blockIdx.y * BM;
    const int bn = blockIdx.x * BN;

    const bf16* Aptr;
    const bf16* Bptr;
    if      constexpr (MODE == 0) { Aptr = g_xbf;     Bptr = g_wqkv; }
    else if constexpr (MODE == 1) { Aptr = g_attnout; Bptr = g_wproj; }
    else if constexpr (MODE == 2) { Aptr = g_x1n;     Bptr = g_w1; }
    else                          { Aptr = g_h;       Bptr = g_w2; }

    int grA;
    if constexpr (MODE == 0) grA = map_win_to_global(bm + tid);
    else                     grA = bm + tid;
    const bf16* srcA = Aptr + (size_t)grA * KDIM;
    const uint32_t dA = smem_u32(sA) + (uint32_t)(tid * LDA * 2);

    const int bR0 = tid >> 3,         bC0 = (tid & 7) * 8;
    const int bR1 = (tid + 128) >> 3, bC1 = (tid & 7) * 8;
    const bf16* srcB0 = Bptr + (size_t)bR0 * NDIM + bn + bC0;
    const bf16* srcB1 = Bptr + (size_t)bR1 * NDIM + bn + bC1;
    const uint32_t dB0 = smem_u32(sB) + (uint32_t)((bR0 * LDB + bC0) * 2);
    const uint32_t dB1 = smem_u32(sB) + (uint32_t)((bR1 * LDB + bC1) * 2);

    constexpr int T = KDIM / BK;
    const int wid = tid >> 5;
    const int wm = wid & 1, wn = wid >> 1;

    wmma::fragment<wmma::accumulator, 16, 16, 16, float> cf[4][2];
    #pragma unroll
    for (int i = 0; i < 4; i++)
        #pragma unroll
        for (int j = 0; j < 2; j++) wmma::fill_fragment(cf[i][j], 0.0f);

    #pragma unroll
    for (int c = 0; c < 4; c++) CP_ASYNC16(dA + c * 16, srcA + c * 8);
    CP_ASYNC16(dB0, srcB0);
    CP_ASYNC16(dB1, srcB1);
    CP_COMMIT();

    for (int t = 0; t < T; t++) {
        if (t + 1 < T) {
            const int k0 = (t + 1) * BK;
            const uint32_t soA = ((t + 1) & 1) ? A_STAGE_B : 0;
            const uint32_t soB = ((t + 1) & 1) ? B_STAGE_B : 0;
            #pragma unroll
            for (int c = 0; c < 4; c++) CP_ASYNC16(dA + soA + c * 16, srcA + k0 + c * 8);
            CP_ASYNC16(dB0 + soB, srcB0 + (size_t)k0 * NDIM);
            CP_ASYNC16(dB1 + soB, srcB1 + (size_t)k0 * NDIM);
            CP_COMMIT();
            CP_WAIT(1);
        } else {
            CP_WAIT(0);
        }
        __syncthreads();

        const bf16* At = sA + ((t & 1) ? BM * LDA : 0);
        const bf16* Bt = sB + ((t & 1) ? BK * LDB : 0);

        #pragma unroll
        for (int kk = 0; kk < BK; kk += 16) {
            wmma::fragment<wmma::matrix_a, 16, 16, 16, bf16, wmma::row_major> af[4];
            wmma::fragment<wmma::matrix_b, 16, 16, 16, bf16, wmma::row_major> bf_[2];
            #pragma unroll
            for (int i = 0; i < 4; i++)
                wmma::load_matrix_sync(af[i], At + (wm * 64 + i * 16) * LDA + kk, LDA);
            #pragma unroll
            for (int j = 0; j < 2; j++)
                wmma::load_matrix_sync(bf_[j], Bt + kk * LDB + wn * 32 + j * 16, LDB);
            #pragma unroll
            for (int i = 0; i < 4; i++)
                #pragma unroll
                for (int j = 0; j < 2; j++)
                    wmma::mma_sync(cf[i][j], af[i], bf_[j], cf[i][j]);
        }
        __syncthreads();
    }

    #pragma unroll
    for (int i = 0; i < 4; i++)
        #pragma unroll
        for (int j = 0; j < 2; j++)
            wmma::store_matrix_sync(sC + (wm * 64 + i * 16) * LDC + wn * 32 + j * 16,
                                    cf[i][j], LDC, wmma::mem_row_major);
    __syncthreads();

    const int m = bm + tid;
    float v[64];
    #pragma unroll
    for (int c4 = 0; c4 < 16; c4++) {
        float4 w4 = *(const float4*)(sC + tid * LDC + c4 * 4);
        v[c4*4+0] = w4.x + __ldg(bias + bn + c4*4 + 0);
        v[c4*4+1] = w4.y + __ldg(bias + bn + c4*4 + 1);
        v[c4*4+2] = w4.z + __ldg(bias + bn + c4*4 + 2);
        v[c4*4+3] = w4.w + __ldg(bias + bn + c4*4 + 3);
    }

    if constexpr (MODE == 0) {
        bf16* dst = g_qkv + (size_t)m * QKVN + bn;
        #pragma unroll
        for (int g = 0; g < 8; g++) {
            uint4 o;
            o.x = pack_bf2(v[g*8+0], v[g*8+1]); o.y = pack_bf2(v[g*8+2], v[g*8+3]);
            o.z = pack_bf2(v[g*8+4], v[g*8+5]); o.w = pack_bf2(v[g*8+6], v[g*8+7]);
            *(uint4*)(dst + g * 8) = o;
        }
    } else if constexpr (MODE == 1) {
        const int grow = map_win_to_global(m);
        const size_t o = (size_t)grow * CDIM + bn;
        #pragma unroll
        for (int c4 = 0; c4 < 16; c4++) {
            float4 r = *(const float4*)(resid + o + c4 * 4);
            *(float4*)(g_x1 + o + c4 * 4) =
                make_float4(v[c4*4+0] + r.x, v[c4*4+1] + r.y, v[c4*4+2] + r.z, v[c4*4+3] + r.w);
        }
    } else if constexpr (MODE == 2) {
        bf16* dst = g_h + (size_t)m * HID + bn;
        #pragma unroll
        for (int g = 0; g < 8; g++) {
            uint4 o;
            o.x = pack_bf2(gelu_exact(v[g*8+0]), gelu_exact(v[g*8+1]));
            o.y = pack_bf2(gelu_exact(v[g*8+2]), gelu_exact(v[g*8+3]));
            o.z = pack_bf2(gelu_exact(v[g*8+4]), gelu_exact(v[g*8+5]));
            o.w = pack_bf2(gelu_exact(v[g*8+6]), gelu_exact(v[g*8+7]));
            *(uint4*)(dst + g * 8) = o;
        }
    } else {
        const size_t o = (size_t)m * CDIM + bn;
        #pragma unroll
        for (int c4 = 0; c4 < 16; c4++) {
            float4 r = *(const float4*)(g_x1 + o + c4 * 4);
            *(float4*)(Cout + o + c4 * 4) =
                make_float4(v[c4*4+0] + r.x, v[c4*4+1] + r.y, v[c4*4+2] + r.z, v[c4*4+3] + r.w);
        }
    }
}

// ---------------- LayerNorm: one warp per token, bf16 out ---------------------
__global__ void __launch_bounds__(256) ln_norm_k(const float* __restrict__ gamma,
                                                 const float* __restrict__ beta)
{
    const int r = blockIdx.x * 8 + (threadIdx.x >> 5);
    const int lane = threadIdx.x & 31;
    const float* p = g_x1 + (size_t)r * CDIM;
    float v[6];
    float s = 0.f, ss = 0.f;
    #pragma unroll
    for (int k = 0; k < 6; k++) {
        v[k] = p[lane + k * 32];
        s += v[k]; ss += v[k] * v[k];
    }
    #pragma unroll
    for (int o = 16; o; o >>= 1) {
        s  += __shfl_xor_sync(0xffffffffu, s,  o);
        ss += __shfl_xor_sync(0xffffffffu, ss, o);
    }
    const float mu = s * (1.f / 192.f);
    const float var = ss * (1.f / 192.f) - mu * mu;
    const float rs = rsqrtf(var + 1e-5f);
    bf16* q = g_x1n + (size_t)r * CDIM;
    #pragma unroll
    for (int k = 0; k < 6; k++) {
        const int c = lane + k * 32;
        q[c] = __float2bfloat16_rn((v[k] - mu) * rs * __ldg(gamma + c) + __ldg(beta + c));
    }
}

// ---------------- attention: WMMA tensor-core version -------------------------
// One block = one (window, head). 128 threads = 4 warps, warp owns 16 query rows.
// S = Q@K^T (bf16 WMMA, fp32 acc) -> smem; softmax (bias+mask, 1/sum folded into
// P); O = P@V (bf16 WMMA) -> write bf16.
#define ALQ 40     // bf16 ld for Q/K/V tiles
#define ALS 68     // fp32 ld for S (and 36 for O reuse)
#define ALP 72     // bf16 ld for P
#define OFF_K 0
#define OFF_V 5120
#define OFF_Q 10240
#define OFF_S 15360
#define OFF_P 32768
#define ATT_SMEM (32768 + 64 * ALP * 2)   // 41984

__global__ void __launch_bounds__(128) attn_tc(const float* __restrict__ rpb)
{
    const int w = blockIdx.x, head = blockIdx.y;
    const int tid = threadIdx.x;
    const int wid = tid >> 5;

    __shared__ __align__(16) unsigned char buf[ATT_SMEM];
    bf16*  sK = (bf16*)(buf + OFF_K);
    bf16*  sV = (bf16*)(buf + OFF_V);
    bf16*  sQ = (bf16*)(buf + OFF_Q);
    float* sS = (float*)(buf + OFF_S);
    bf16*  sP = (bf16*)(buf + OFF_P);
    __shared__ float sRp[225];
    __shared__ int   sReg[64];

    // load Q,K,V tiles (bf16 -> bf16 straight copies)
    const bf16* base = g_qkv + (size_t)w * 64 * QKVN + head * 32;
    #pragma unroll
    for (int l = 0; l < 2; l++) {
        int i = tid + l * 128;               // 0..255
        int row = i >> 2, cg = (i & 3) * 8;
        const bf16* src = base + (size_t)row * QKVN;
        *(uint4*)(sQ + row * ALQ + cg) = *(const uint4*)(src + cg);
        *(uint4*)(sK + row * ALQ + cg) = *(const uint4*)(src + CDIM + cg);
        *(uint4*)(sV + row * ALQ + cg) = *(const uint4*)(src + 2 * CDIM + cg);
    }
    for (int i = tid; i < 225; i += 128) sRp[i] = rpb[i * NHEAD + head];
    if (tid < 64) {
        int rem = w & 255; int wh = rem >> 4, ww = rem & 15;
        int hs  = wh * 8 + (tid >> 3);
        int wsc = ww * 8 + (tid & 7);
        int rh = hs  < 120 ? 0 : (hs  < 124 ? 1 : 2);
        int rw = wsc < 120 ? 0 : (wsc < 124 ? 1 : 2);
        sReg[tid] = rh * 3 + rw;
    }
    __syncthreads();

    // ---- S = Q @ K^T : warp computes rows [16*wid, 16*wid+16) x all 64 cols
    {
        wmma::fragment<wmma::matrix_a, 16, 16, 16, bf16, wmma::row_major> aq[2];
        wmma::load_matrix_sync(aq[0], sQ + wid * 16 * ALQ + 0,  ALQ);
        wmma::load_matrix_sync(aq[1], sQ + wid * 16 * ALQ + 16, ALQ);
        #pragma unroll
        for (int n = 0; n < 4; n++) {
            wmma::fragment<wmma::accumulator, 16, 16, 16, float> s;
            wmma::fill_fragment(s, 0.0f);
            #pragma unroll
            for (int k = 0; k < 2; k++) {
                wmma::fragment<wmma::matrix_b, 16, 16, 16, bf16, wmma::col_major> bk;
                wmma::load_matrix_sync(bk, sK + n * 16 * ALQ + k * 16, ALQ);
                wmma::mma_sync(s, aq[k], bk, s);
            }
            wmma::store_matrix_sync(sS + wid * 16 * ALS + n * 16, s, ALS, wmma::mem_row_major);
        }
    }
    __syncthreads();

    // ---- softmax: 2 threads per row (halves of 32 cols); fold 1/sum into P
    {
        const int row = tid >> 1, half = tid & 1;
        const int i1 = row >> 3, j1 = row & 7;
        const int regr = sReg[row];
        const float scale = 0.17677669529663689f;
        float e[32];
        float sum = 0.f;
        #pragma unroll
        for (int c = 0; c < 32; c++) {
            const int col = half * 32 + c;
            const int i2 = col >> 3, j2 = col & 7;
            const float b = sRp[(i1 - i2 + 7) * 15 + (j1 - j2 + 7)];
            const float msk = (sReg[col] == regr) ? 0.f : -100.f;
            const float ev = __expf(sS[row * ALS + col] * scale + b + msk);
            e[c] = ev; sum += ev;
        }
        sum += __shfl_xor_sync(0xffffffffu, sum, 1);
        const float inv = 1.f / sum;
        #pragma unroll
        for (int c = 0; c < 32; c += 2)
            *(uint32_t*)(sP + row * ALP + half * 32 + c) = pack_bf2(e[c] * inv, e[c+1] * inv);
    }
    __syncthreads();

    // ---- O = P @ V : warp computes rows [16*wid,16*wid+16) x 32 dims -> sS(ld 36)
    {
        wmma::fragment<wmma::matrix_a, 16, 16, 16, bf16, wmma::row_major> ap[4];
        #pragma unroll
        for (int k = 0; k < 4; k++)
            wmma::load_matrix_sync(ap[k], sP + wid * 16 * ALP + k * 16, ALP);
        #pragma unroll
        for (int d = 0; d < 2; d++) {
            wmma::fragment<wmma::accumulator, 16, 16, 16, float> o;
            wmma::fill_fragment(o, 0.0f);
            #pragma unroll
            for (int k = 0; k < 4; k++) {
                wmma::fragment<wmma::matrix_b, 16, 16, 16, bf16, wmma::row_major> bv;
                wmma::load_matrix_sync(bv, sV + k * 16 * ALQ + d * 16, ALQ);
                wmma::mma_sync(o, ap[k], bv, o);
            }
            wmma::store_matrix_sync(sS + wid * 16 * 36 + d * 16, o, 36, wmma::mem_row_major);
        }
    }
    __syncthreads();

    // ---- write out: thread owns (row, 16-col half) -> bf16
    {
        const int row = tid >> 1, half = tid & 1;
        const float* src = sS + row * 36 + half * 16;
        float4 f0 = *(const float4*)(src + 0);
        float4 f1 = *(const float4*)(src + 4);
        float4 f2 = *(const float4*)(src + 8);
        float4 f3 = *(const float4*)(src + 12);
        uint4 o;
        o.x = pack_bf2(f0.x, f0.y) ;
        uint32_t t1 = pack_bf2(f0.z, f0.w);
        o.x = pack_bf2(f0.x, f0.y); o.y = pack_bf2(f0.z, f0.w);
        o.z = pack_bf2(f1.x, f1.y); o.w = pack_bf2(f1.z, f1.w);
        uint4 o2;
        o2.x = pack_bf2(f2.x, f2.y); o2.y = pack_bf2(f2.z, f2.w);
        o2.z = pack_bf2(f3.x, f3.y); o2.w = pack_bf2(f3.z, f3.w);
        (void)t1;
        bf16* op = g_attnout + ((size_t)(w * 64 + row)) * CDIM + head * 32 + half * 16;
        *(uint2*)(op + 0)  = make_uint2(o.x, o.y);
        *(uint2*)(op + 4)  = make_uint2(o.z, o.w);
        *(uint2*)(op + 8)  = make_uint2(o2.x, o2.y);
        *(uint2*)(op + 12) = make_uint2(o2.z, o2.w);
    }
}

// ---------------- launch -----------------------------------------------------
extern "C" void kernel_launch(void* const* d_in, const int* in_sizes, int n_in,
                              void* d_out, int out_size)
{
    const float* x       = (const float*)d_in[0];
    const float* qkv_w   = (const float*)d_in[1];
    const float* qkv_b   = (const float*)d_in[2];
    const float* proj_w  = (const float*)d_in[3];
    const float* proj_b  = (const float*)d_in[4];
    const float* rpb     = (const float*)d_in[5];
    const float* norm2_g = (const float*)d_in[6];
    const float* norm2_b = (const float*)d_in[7];
    const float* mlp_w1  = (const float*)d_in[8];
    const float* mlp_b1  = (const float*)d_in[9];
    const float* mlp_w2  = (const float*)d_in[10];
    const float* mlp_b2  = (const float*)d_in[11];
    float* out = (float*)d_out;

    // precision conversions
    conv_x_k<<<TOK * CDIM / (256 * 8), 256>>>(x);
    conv_w_all<<<(S0 + S1 + S2 + S3) / (256 * 8), 256>>>(qkv_w, proj_w, mlp_w1, mlp_w2);

    // 1) QKV = gather(x) @ qkv_w + b  -> bf16 g_qkv (window order)
    gemm_bf<192, 576, 0><<<dim3(9, 1024), 128>>>(qkv_b, nullptr, nullptr);
    // 2) windowed attention (tensor cores) -> bf16 g_attnout
    attn_tc<<<dim3(NWIN, NHEAD), 128>>>(rpb);
    // 3) proj + scatter + residual -> fp32 g_x1
    gemm_bf<192, 192, 1><<<dim3(3, 1024), 128>>>(proj_b, x, nullptr);
    // 4) LayerNorm(g_x1) -> bf16 g_x1n
    ln_norm_k<<<TOK / 8, 256>>>(norm2_g, norm2_b);
    // 5) fc1 + GELU -> bf16 g_h
    gemm_bf<192, 768, 2><<<dim3(12, 1024), 128>>>(mlp_b1, nullptr, nullptr);
    // 6) fc2 + residual -> fp32 out
    gemm_bf<768, 192, 3><<<dim3(3, 1024), 128>>>(mlp_b2, nullptr, out);
}

// round 9
// speedup vs baseline: 1.3822x; 1.1474x over previous
#include <cuda_runtime.h>
#include <cuda_bf16.h>
#include <mma.h>
#include <cstdint>
#include <math.h>

using namespace nvcuda;
typedef __nv_bfloat16 bf16;

// Problem constants (fixed shapes)
#define TOK   131072      // B*H*W = 8*128*128
#define CDIM  192
#define HID   768
#define QKVN  576
#define NHEAD 6
#define SS    4
#define NWIN  2048        // B * 16 * 16

// GEMM tiling: block 128x96, 4 warps (2m x 2n), warp tile 64x48
#define BM 128
#define BN 96
#define BK 32
#define LDA 40            // bf16 ld, 80B rows
#define LDB 104           // bf16 ld for B (96+8)
#define LDC 100           // fp32 ld for C half-tile
#define A_STAGE_B (BM * LDA * 2)      // 10240 B
#define B_STAGE_B (BK * LDB * 2)      // 6656 B
#define STAGE_B   (A_STAGE_B + B_STAGE_B)
#define SMEM_BYTES (2 * STAGE_B)      // 33792; C half-tile 64*100*4=25600 fits

// ---------------- scratch (device globals; no allocations allowed) ----------
__device__ bf16  g_xbf[TOK * CDIM];
__device__ bf16  g_qkv[TOK * QKVN];        // window-ordered, bf16
__device__ bf16  g_attnout[TOK * CDIM];    // window-ordered, bf16
__device__ float g_x1[TOK * CDIM];         // fp32 residual spine
__device__ bf16  g_x1n[TOK * CDIM];
__device__ bf16  g_h[TOK * HID];
__device__ bf16  g_wqkv[CDIM * QKVN];
__device__ bf16  g_wproj[CDIM * CDIM];
__device__ bf16  g_w1[CDIM * HID];
__device__ bf16  g_w2[HID * CDIM];

// ---------------- helpers ----------------------------------------------------
__device__ __forceinline__ uint32_t smem_u32(const void* p) {
    uint32_t a;
    asm("{ .reg .u64 t; cvta.to.shared.u64 t, %1; cvt.u32.u64 %0, t; }" : "=r"(a) : "l"(p));
    return a;
}
#define CP_ASYNC16(dst, src) \
    asm volatile("cp.async.cg.shared.global [%0], [%1], 16;" :: "r"(dst), "l"(src))
#define CP_COMMIT() asm volatile("cp.async.commit_group;" ::: "memory")
#define CP_WAIT(n)  asm volatile("cp.async.wait_group %0;" :: "n"(n) : "memory")

__device__ __forceinline__ int map_win_to_global(int r) {
    int w = r >> 6, n = r & 63;
    int b = w >> 8, rem = w & 255;
    int wh = rem >> 4, ww = rem & 15;
    int i = n >> 3, j = n & 7;
    int h  = (wh * 8 + i + SS) & 127;
    int wc = (ww * 8 + j + SS) & 127;
    return (b << 14) + (h << 7) + wc;
}
__device__ __forceinline__ float gelu_exact(float v) {
    return 0.5f * v * (1.0f + erff(v * 0.70710678118654752440f));
}
__device__ __forceinline__ uint32_t pack_bf2(float a, float b) {
    __nv_bfloat162 h = __floats2bfloat162_rn(a, b);
    return *(uint32_t*)&h;
}

// ---------------- fp32 -> bf16 conversion -------------------------------------
__global__ void __launch_bounds__(256) conv_x_k(const float* __restrict__ src) {
    const size_t i = ((size_t)blockIdx.x * 256 + threadIdx.x) * 8;
    float4 v0 = *(const float4*)(src + i);
    float4 v1 = *(const float4*)(src + i + 4);
    uint4 o;
    o.x = pack_bf2(v0.x, v0.y); o.y = pack_bf2(v0.z, v0.w);
    o.z = pack_bf2(v1.x, v1.y); o.w = pack_bf2(v1.z, v1.w);
    *(uint4*)(g_xbf + i) = o;
}
#define S0 (CDIM*QKVN)
#define S1 (CDIM*CDIM)
#define S2 (CDIM*HID)
#define S3 (HID*CDIM)
__global__ void __launch_bounds__(256) conv_w_all(
    const float* __restrict__ w0, const float* __restrict__ w1,
    const float* __restrict__ w2, const float* __restrict__ w3)
{
    const int off = (blockIdx.x * 256 + threadIdx.x) * 8;
    const float* src; bf16* dst; int lo;
    if      (off < S0)            { src = w0; dst = g_wqkv;  lo = off; }
    else if (off < S0+S1)         { src = w1; dst = g_wproj; lo = off - S0; }
    else if (off < S0+S1+S2)      { src = w2; dst = g_w1;    lo = off - S0 - S1; }
    else if (off < S0+S1+S2+S3)   { src = w3; dst = g_w2;    lo = off - S0 - S1 - S2; }
    else return;
    float4 v0 = *(const float4*)(src + lo);
    float4 v1 = *(const float4*)(src + lo + 4);
    uint4 o;
    o.x = pack_bf2(v0.x, v0.y); o.y = pack_bf2(v0.z, v0.w);
    o.z = pack_bf2(v1.x, v1.y); o.w = pack_bf2(v1.z, v1.w);
    *(uint4*)(dst + lo) = o;
}

// ---------------- WMMA bf16 GEMM: 128x96 block, 64x48 warp tile ---------------
// MODE: 0=QKV(gather A; out bf16 g_qkv)  1=PROJ(scatter+resid -> fp32 g_x1)
//       2=FC1(gelu -> bf16 g_h)          3=FC2(+resid g_x1 -> fp32 Cout)
template<int KDIM, int NDIM, int MODE>
__global__ void __launch_bounds__(128) gemm_bf(
    const float* __restrict__ bias,
    const float* __restrict__ resid,
    float* __restrict__ Cout)
{
    __shared__ __align__(16) unsigned char smem[SMEM_BYTES];
    bf16* sA[2] = { (bf16*)smem, (bf16*)(smem + STAGE_B) };
    bf16* sB[2] = { (bf16*)(smem + A_STAGE_B), (bf16*)(smem + STAGE_B + A_STAGE_B) };
    float* sC = (float*)smem;   // 64x100 fp32 half-tile, aliases pipeline smem

    const int tid = threadIdx.x;
    const int bm = blockIdx.y * BM;
    const int bn = blockIdx.x * BN;

    const bf16* Aptr;
    const bf16* Bptr;
    if      constexpr (MODE == 0) { Aptr = g_xbf;     Bptr = g_wqkv; }
    else if constexpr (MODE == 1) { Aptr = g_attnout; Bptr = g_wproj; }
    else if constexpr (MODE == 2) { Aptr = g_x1n;     Bptr = g_w1; }
    else                          { Aptr = g_h;       Bptr = g_w2; }

    // A: thread owns row tid (32 bf16 = 4 x 16B)
    int grA;
    if constexpr (MODE == 0) grA = map_win_to_global(bm + tid);
    else                     grA = bm + tid;
    const bf16* srcA = Aptr + (size_t)grA * KDIM;
    const uint32_t dA0 = smem_u32(sA[0]) + (uint32_t)(tid * LDA * 2);
    const uint32_t dA1 = smem_u32(sA[1]) + (uint32_t)(tid * LDA * 2);

    // B: 32 rows x 96 bf16 = 384 x 8-elem chunks; 3 per thread
    int bRow[3], bCol[3];
    const bf16* srcB[3];
    uint32_t dBoff[3];
    #pragma unroll
    for (int l = 0; l < 3; l++) {
        int idx = tid + l * 128;               // 0..383
        bRow[l] = idx / 12; bCol[l] = (idx % 12) * 8;   // rows 0..31
        srcB[l] = Bptr + (size_t)bRow[l] * NDIM + bn + bCol[l];
        dBoff[l] = (uint32_t)((bRow[l] * LDB + bCol[l]) * 2);
    }
    const uint32_t dBb[2] = { smem_u32(sB[0]), smem_u32(sB[1]) };

    constexpr int T = KDIM / BK;
    const int wid = tid >> 5;
    const int wm = wid & 1, wn = wid >> 1;   // warp tile 64x48

    wmma::fragment<wmma::accumulator, 16, 16, 16, float> cf[4][3];
    #pragma unroll
    for (int i = 0; i < 4; i++)
        #pragma unroll
        for (int j = 0; j < 3; j++) wmma::fill_fragment(cf[i][j], 0.0f);

    // prefetch stage 0
    #pragma unroll
    for (int c = 0; c < 4; c++) CP_ASYNC16(dA0 + c * 16, srcA + c * 8);
    #pragma unroll
    for (int l = 0; l < 3; l++) CP_ASYNC16(dBb[0] + dBoff[l], srcB[l]);
    CP_COMMIT();

    for (int t = 0; t < T; t++) {
        if (t + 1 < T) {
            const int k0 = (t + 1) * BK;
            const uint32_t dAx = ((t + 1) & 1) ? dA1 : dA0;
            const uint32_t dBx = dBb[(t + 1) & 1];
            #pragma unroll
            for (int c = 0; c < 4; c++) CP_ASYNC16(dAx + c * 16, srcA + k0 + c * 8);
            #pragma unroll
            for (int l = 0; l < 3; l++) CP_ASYNC16(dBx + dBoff[l], srcB[l] + (size_t)k0 * NDIM);
            CP_COMMIT();
            CP_WAIT(1);
        } else {
            CP_WAIT(0);
        }
        __syncthreads();

        const bf16* At = sA[t & 1];
        const bf16* Bt = sB[t & 1];

        #pragma unroll
        for (int kk = 0; kk < BK; kk += 16) {
            wmma::fragment<wmma::matrix_a, 16, 16, 16, bf16, wmma::row_major> af[4];
            wmma::fragment<wmma::matrix_b, 16, 16, 16, bf16, wmma::row_major> bf_[3];
            #pragma unroll
            for (int i = 0; i < 4; i++)
                wmma::load_matrix_sync(af[i], At + (wm * 64 + i * 16) * LDA + kk, LDA);
            #pragma unroll
            for (int j = 0; j < 3; j++)
                wmma::load_matrix_sync(bf_[j], Bt + kk * LDB + wn * 48 + j * 16, LDB);
            #pragma unroll
            for (int i = 0; i < 4; i++)
                #pragma unroll
                for (int j = 0; j < 3; j++)
                    wmma::mma_sync(cf[i][j], af[i], bf_[j], cf[i][j]);
        }
        __syncthreads();
    }

    // ---------------- epilogue: two 64-row passes ------------------------------
    #pragma unroll
    for (int h = 0; h < 2; h++) {
        if (wm == h) {
            #pragma unroll
            for (int i = 0; i < 4; i++)
                #pragma unroll
                for (int j = 0; j < 3; j++)
                    wmma::store_matrix_sync(sC + (i * 16) * LDC + wn * 48 + j * 16,
                                            cf[i][j], LDC, wmma::mem_row_major);
        }
        __syncthreads();

        // 64 rows x 96 cols; thread owns (row = tid>>1, half = tid&1 -> 48 cols)
        const int row  = tid >> 1;
        const int half = tid & 1;
        const int c0   = half * 48;
        const int m    = bm + h * 64 + row;
        float v[48];
        #pragma unroll
        for (int c4 = 0; c4 < 12; c4++) {
            float4 w4 = *(const float4*)(sC + row * LDC + c0 + c4 * 4);
            const int gc = bn + c0 + c4 * 4;
            v[c4*4+0] = w4.x + __ldg(bias + gc + 0);
            v[c4*4+1] = w4.y + __ldg(bias + gc + 1);
            v[c4*4+2] = w4.z + __ldg(bias + gc + 2);
            v[c4*4+3] = w4.w + __ldg(bias + gc + 3);
        }

        if constexpr (MODE == 0) {
            bf16* dst = g_qkv + (size_t)m * QKVN + bn + c0;
            #pragma unroll
            for (int g = 0; g < 6; g++) {
                uint4 o;
                o.x = pack_bf2(v[g*8+0], v[g*8+1]); o.y = pack_bf2(v[g*8+2], v[g*8+3]);
                o.z = pack_bf2(v[g*8+4], v[g*8+5]); o.w = pack_bf2(v[g*8+6], v[g*8+7]);
                *(uint4*)(dst + g * 8) = o;
            }
        } else if constexpr (MODE == 1) {
            const int grow = map_win_to_global(m);
            const size_t o = (size_t)grow * CDIM + bn + c0;
            #pragma unroll
            for (int c4 = 0; c4 < 12; c4++) {
                float4 r = *(const float4*)(resid + o + c4 * 4);
                *(float4*)(g_x1 + o + c4 * 4) =
                    make_float4(v[c4*4+0] + r.x, v[c4*4+1] + r.y, v[c4*4+2] + r.z, v[c4*4+3] + r.w);
            }
        } else if constexpr (MODE == 2) {
            bf16* dst = g_h + (size_t)m * HID + bn + c0;
            #pragma unroll
            for (int g = 0; g < 6; g++) {
                uint4 o;
                o.x = pack_bf2(gelu_exact(v[g*8+0]), gelu_exact(v[g*8+1]));
                o.y = pack_bf2(gelu_exact(v[g*8+2]), gelu_exact(v[g*8+3]));
                o.z = pack_bf2(gelu_exact(v[g*8+4]), gelu_exact(v[g*8+5]));
                o.w = pack_bf2(gelu_exact(v[g*8+6]), gelu_exact(v[g*8+7]));
                *(uint4*)(dst + g * 8) = o;
            }
        } else {
            const size_t o = (size_t)m * CDIM + bn + c0;
            #pragma unroll
            for (int c4 = 0; c4 < 12; c4++) {
                float4 r = *(const float4*)(g_x1 + o + c4 * 4);
                *(float4*)(Cout + o + c4 * 4) =
                    make_float4(v[c4*4+0] + r.x, v[c4*4+1] + r.y, v[c4*4+2] + r.z, v[c4*4+3] + r.w);
            }
        }
        __syncthreads();
    }
}

// ---------------- LayerNorm: one warp per token, bf16 out ---------------------
__global__ void __launch_bounds__(256) ln_norm_k(const float* __restrict__ gamma,
                                                 const float* __restrict__ beta)
{
    const int r = blockIdx.x * 8 + (threadIdx.x >> 5);
    const int lane = threadIdx.x & 31;
    const float* p = g_x1 + (size_t)r * CDIM;
    float v[6];
    float s = 0.f, ss = 0.f;
    #pragma unroll
    for (int k = 0; k < 6; k++) {
        v[k] = p[lane + k * 32];
        s += v[k]; ss += v[k] * v[k];
    }
    #pragma unroll
    for (int o = 16; o; o >>= 1) {
        s  += __shfl_xor_sync(0xffffffffu, s,  o);
        ss += __shfl_xor_sync(0xffffffffu, ss, o);
    }
    const float mu = s * (1.f / 192.f);
    const float var = ss * (1.f / 192.f) - mu * mu;
    const float rs = rsqrtf(var + 1e-5f);
    bf16* q = g_x1n + (size_t)r * CDIM;
    #pragma unroll
    for (int k = 0; k < 6; k++) {
        const int c = lane + k * 32;
        q[c] = __float2bfloat16_rn((v[k] - mu) * rs * __ldg(gamma + c) + __ldg(beta + c));
    }
}

// ---------------- attention: WMMA tensor-core (proven, round 7) ---------------
#define ALQ 40
#define ALS 68
#define ALP 72
#define OFF_K 0
#define OFF_V 5120
#define OFF_Q 10240
#define OFF_S 15360
#define OFF_P 32768
#define ATT_SMEM (32768 + 64 * ALP * 2)

__global__ void __launch_bounds__(128) attn_tc(const float* __restrict__ rpb)
{
    const int w = blockIdx.x, head = blockIdx.y;
    const int tid = threadIdx.x;
    const int wid = tid >> 5;

    __shared__ __align__(16) unsigned char buf[ATT_SMEM];
    bf16*  sK = (bf16*)(buf + OFF_K);
    bf16*  sV = (bf16*)(buf + OFF_V);
    bf16*  sQ = (bf16*)(buf + OFF_Q);
    float* sS = (float*)(buf + OFF_S);
    bf16*  sP = (bf16*)(buf + OFF_P);
    __shared__ float sRp[225];
    __shared__ int   sReg[64];

    const bf16* base = g_qkv + (size_t)w * 64 * QKVN + head * 32;
    #pragma unroll
    for (int l = 0; l < 2; l++) {
        int i = tid + l * 128;
        int row = i >> 2, cg = (i & 3) * 8;
        const bf16* src = base + (size_t)row * QKVN;
        *(uint4*)(sQ + row * ALQ + cg) = *(const uint4*)(src + cg);
        *(uint4*)(sK + row * ALQ + cg) = *(const uint4*)(src + CDIM + cg);
        *(uint4*)(sV + row * ALQ + cg) = *(const uint4*)(src + 2 * CDIM + cg);
    }
    for (int i = tid; i < 225; i += 128) sRp[i] = rpb[i * NHEAD + head];
    if (tid < 64) {
        int rem = w & 255; int wh = rem >> 4, ww = rem & 15;
        int hs  = wh * 8 + (tid >> 3);
        int wsc = ww * 8 + (tid & 7);
        int rh = hs  < 120 ? 0 : (hs  < 124 ? 1 : 2);
        int rw = wsc < 120 ? 0 : (wsc < 124 ? 1 : 2);
        sReg[tid] = rh * 3 + rw;
    }
    __syncthreads();

    {
        wmma::fragment<wmma::matrix_a, 16, 16, 16, bf16, wmma::row_major> aq[2];
        wmma::load_matrix_sync(aq[0], sQ + wid * 16 * ALQ + 0,  ALQ);
        wmma::load_matrix_sync(aq[1], sQ + wid * 16 * ALQ + 16, ALQ);
        #pragma unroll
        for (int n = 0; n < 4; n++) {
            wmma::fragment<wmma::accumulator, 16, 16, 16, float> s;
            wmma::fill_fragment(s, 0.0f);
            #pragma unroll
            for (int k = 0; k < 2; k++) {
                wmma::fragment<wmma::matrix_b, 16, 16, 16, bf16, wmma::col_major> bk;
                wmma::load_matrix_sync(bk, sK + n * 16 * ALQ + k * 16, ALQ);
                wmma::mma_sync(s, aq[k], bk, s);
            }
            wmma::store_matrix_sync(sS + wid * 16 * ALS + n * 16, s, ALS, wmma::mem_row_major);
        }
    }
    __syncthreads();

    {
        const int row = tid >> 1, half = tid & 1;
        const int i1 = row >> 3, j1 = row & 7;
        const int regr = sReg[row];
        const float scale = 0.17677669529663689f;
        float e[32];
        float sum = 0.f;
        #pragma unroll
        for (int c = 0; c < 32; c++) {
            const int col = half * 32 + c;
            const int i2 = col >> 3, j2 = col & 7;
            const float b = sRp[(i1 - i2 + 7) * 15 + (j1 - j2 + 7)];
            const float msk = (sReg[col] == regr) ? 0.f : -100.f;
            const float ev = __expf(sS[row * ALS + col] * scale + b + msk);
            e[c] = ev; sum += ev;
        }
        sum += __shfl_xor_sync(0xffffffffu, sum, 1);
        const float inv = 1.f / sum;
        #pragma unroll
        for (int c = 0; c < 32; c += 2)
            *(uint32_t*)(sP + row * ALP + half * 32 + c) = pack_bf2(e[c] * inv, e[c+1] * inv);
    }
    __syncthreads();

    {
        wmma::fragment<wmma::matrix_a, 16, 16, 16, bf16, wmma::row_major> ap[4];
        #pragma unroll
        for (int k = 0; k < 4; k++)
            wmma::load_matrix_sync(ap[k], sP + wid * 16 * ALP + k * 16, ALP);
        #pragma unroll
        for (int d = 0; d < 2; d++) {
            wmma::fragment<wmma::accumulator, 16, 16, 16, float> o;
            wmma::fill_fragment(o, 0.0f);
            #pragma unroll
            for (int k = 0; k < 4; k++) {
                wmma::fragment<wmma::matrix_b, 16, 16, 16, bf16, wmma::row_major> bv;
                wmma::load_matrix_sync(bv, sV + k * 16 * ALQ + d * 16, ALQ);
                wmma::mma_sync(o, ap[k], bv, o);
            }
            wmma::store_matrix_sync(sS + wid * 16 * 36 + d * 16, o, 36, wmma::mem_row_major);
        }
    }
    __syncthreads();

    {
        const int row = tid >> 1, half = tid & 1;
        const float* src = sS + row * 36 + half * 16;
        float4 f0 = *(const float4*)(src + 0);
        float4 f1 = *(const float4*)(src + 4);
        float4 f2 = *(const float4*)(src + 8);
        float4 f3 = *(const float4*)(src + 12);
        bf16* op = g_attnout + ((size_t)(w * 64 + row)) * CDIM + head * 32 + half * 16;
        *(uint2*)(op + 0)  = make_uint2(pack_bf2(f0.x, f0.y), pack_bf2(f0.z, f0.w));
        *(uint2*)(op + 4)  = make_uint2(pack_bf2(f1.x, f1.y), pack_bf2(f1.z, f1.w));
        *(uint2*)(op + 8)  = make_uint2(pack_bf2(f2.x, f2.y), pack_bf2(f2.z, f2.w));
        *(uint2*)(op + 12) = make_uint2(pack_bf2(f3.x, f3.y), pack_bf2(f3.z, f3.w));
    }
}

// ---------------- launch -----------------------------------------------------
extern "C" void kernel_launch(void* const* d_in, const int* in_sizes, int n_in,
                              void* d_out, int out_size)
{
    const float* x       = (const float*)d_in[0];
    const float* qkv_w   = (const float*)d_in[1];
    const float* qkv_b   = (const float*)d_in[2];
    const float* proj_w  = (const float*)d_in[3];
    const float* proj_b  = (const float*)d_in[4];
    const float* rpb     = (const float*)d_in[5];
    const float* norm2_g = (const float*)d_in[6];
    const float* norm2_b = (const float*)d_in[7];
    const float* mlp_w1  = (const float*)d_in[8];
    const float* mlp_b1  = (const float*)d_in[9];
    const float* mlp_w2  = (const float*)d_in[10];
    const float* mlp_b2  = (const float*)d_in[11];
    float* out = (float*)d_out;

    // precision conversions
    conv_x_k<<<TOK * CDIM / (256 * 8), 256>>>(x);
    conv_w_all<<<(S0 + S1 + S2 + S3) / (256 * 8), 256>>>(qkv_w, proj_w, mlp_w1, mlp_w2);

    // 1) QKV = gather(x) @ qkv_w + b  -> bf16 g_qkv (window order)
    gemm_bf<192, 576, 0><<<dim3(6, 1024), 128>>>(qkv_b, nullptr, nullptr);
    // 2) windowed attention (tensor cores) -> bf16 g_attnout
    attn_tc<<<dim3(NWIN, NHEAD), 128>>>(rpb);
    // 3) proj + scatter + residual -> fp32 g_x1
    gemm_bf<192, 192, 1><<<dim3(2, 1024), 128>>>(proj_b, x, nullptr);
    // 4) LayerNorm(g_x1) -> bf16 g_x1n
    ln_norm_k<<<TOK / 8, 256>>>(norm2_g, norm2_b);
    // 5) fc1 + GELU -> bf16 g_h
    gemm_bf<192, 768, 2><<<dim3(8, 1024), 128>>>(mlp_b1, nullptr, nullptr);
    // 6) fc2 + residual -> fp32 out
    gemm_bf<768, 192, 3><<<dim3(2, 1024), 128>>>(mlp_b2, nullptr, out);
}